// round 14
// baseline (speedup 1.0000x reference)
#include <cuda_runtime.h>
#include <cuda_fp16.h>
#include <mma.h>
#include <cstdint>
#include <math.h>

using namespace nvcuda;

#define TT 64
#define BB 64
#define EE 256
#define HH 512
#define VV 32000
#define G3 1536                      // 3H
#define KAB 768                      // H + E
#define MENC (TT*BB)                 // 4096
#define MDEC ((TT-1)*BB)             // 4032
#define MPAD 4096
#define NT 250                       // N tiles of 128
#define BVOFF ((size_t)BB*VV)
#define LOSS_IDX ((size_t)TT*BB*VV)
#define NSTEP (2*TT - 1)
#define NCTA_GRU 64
#define CONVW_BLKS ((VV * KAB) / 8 / 256)          // 12000
#define CONVW_PLANES ((CONVW_BLKS + 23) / 24)      // 500
#define ZERO_SLOTS 526336
#define ZERO_PLANES ((ZERO_SLOTS + 24*256 - 1) / (24*256))   // 86
#define GATES_PLANES (127 + CONVW_PLANES + ZERO_PLANES)      // 713

typedef unsigned long long u64;

// ---------------- scratch -----------------------------------------------------
__device__ float g_xg[MENC * G3];
__device__ float g_yg[MDEC * G3];
__device__ __align__(256) __half g_Ah[MPAD * KAB];
__device__ __align__(256) __half g_Wh[VV * KAB];
__device__ __align__(256) float g_h [2][BB * HH];
__device__ float g_lse[MDEC];
__device__ float g_pmax[MDEC * NT];
__device__ float g_psum[MDEC * NT];
__device__ unsigned g_cnt2 = 0;                // monotonic barrier counter
__device__ unsigned g_base = 0;                // snapshot (set in gates kernel)

// ================= helpers ===================================================
__device__ __forceinline__ uint32_t smem_u32(const void* p) {
    uint32_t a;
    asm("{ .reg .u64 t; cvta.to.shared.u64 t, %1; cvt.u32.u64 %0, t; }" : "=r"(a) : "l"(p));
    return a;
}
__device__ __forceinline__ void cp_async16(uint32_t dst, const void* src) {
    asm volatile("cp.async.cg.shared.global [%0], [%1], 16;" :: "r"(dst), "l"(src));
}
#define CP_COMMIT() asm volatile("cp.async.commit_group;" ::: "memory")

// ------- merged: gate GEMMs ∪ Wout fp32->fp16 ∪ zero-init --------------------
__global__ void k_gates(const int* __restrict__ x, const int* __restrict__ y,
                        const float* __restrict__ emb,
                        const float* __restrict__ eW, const float* __restrict__ eb,
                        const float* __restrict__ dW, const float* __restrict__ db,
                        const float* __restrict__ Wout,
                        float* __restrict__ dout)
{
    __shared__ float As[32][64];
    __shared__ float Bs[32][64];
    __shared__ int   sidx[64];

    int by = blockIdx.y;
    int tid = threadIdx.x;

    if (by >= 127 + CONVW_PLANES) {        // ---- zero planes ----
        int chunk = (by - (127 + CONVW_PLANES)) * 24 + blockIdx.x;
        size_t slot = (size_t)chunk * 256 + tid;
        if (slot < ZERO_SLOTS) {
            float4 z = make_float4(0.f, 0.f, 0.f, 0.f);
            if (slot < 512000)        ((float4*)dout)[slot] = z;
            else if (slot < 520192)   ((float4*)g_h[0])[slot - 512000] = z;
            else                      ((float4*)(g_Ah + (size_t)MDEC * KAB))[slot - 520192] = z;
        }
        return;
    }

    if (by >= 127) {                       // ---- convW planes ----
        if (by == 127 && blockIdx.x == 0 && tid == 0)
            g_base = *(volatile unsigned*)&g_cnt2;
        int chunk = (by - 127) * 24 + blockIdx.x;
        size_t i = ((size_t)chunk * 256 + tid) * 8;
        if (i < (size_t)VV * KAB) {
            float4 a = *(const float4*)(Wout + i);
            float4 b = *(const float4*)(Wout + i + 4);
            __half2 h0 = __floats2half2_rn(a.x, a.y);
            __half2 h1 = __floats2half2_rn(a.z, a.w);
            __half2 h2 = __floats2half2_rn(b.x, b.y);
            __half2 h3 = __floats2half2_rn(b.z, b.w);
            uint4 o;
            o.x = *(uint32_t*)&h0; o.y = *(uint32_t*)&h1;
            o.z = *(uint32_t*)&h2; o.w = *(uint32_t*)&h3;
            *(uint4*)(g_Wh + i) = o;
        }
        return;
    }

    int is_dec = (by >= 64);
    const int*   idx = is_dec ? y  : x;
    const float* Wih = is_dec ? dW : eW;
    const float* bih = is_dec ? db : eb;
    float* __restrict__ out = is_dec ? g_yg : g_xg;
    int r0 = (is_dec ? (by - 64) : by) * 64;
    int c0 = blockIdx.x * 64;

    if (tid < 64) sidx[tid] = idx[r0 + tid];
    __syncthreads();

    int tx = tid & 15, ty = tid >> 4;
    float acc[4][4] = {};

    for (int k0 = 0; k0 < EE; k0 += 32) {
        #pragma unroll
        for (int fi = tid; fi < 512; fi += 256) {
            int r = fi >> 3, kq = (fi & 7) * 4;
            float4 v = *(const float4*)(emb + (size_t)sidx[r] * EE + k0 + kq);
            As[kq + 0][r] = v.x; As[kq + 1][r] = v.y;
            As[kq + 2][r] = v.z; As[kq + 3][r] = v.w;
        }
        #pragma unroll
        for (int fi = tid; fi < 512; fi += 256) {
            int c = fi >> 3, kq = (fi & 7) * 4;
            float4 v = *(const float4*)(Wih + (size_t)(c0 + c) * EE + k0 + kq);
            Bs[kq + 0][c] = v.x; Bs[kq + 1][c] = v.y;
            Bs[kq + 2][c] = v.z; Bs[kq + 3][c] = v.w;
        }
        __syncthreads();
        #pragma unroll
        for (int k = 0; k < 32; k++) {
            float4 a = *(const float4*)&As[k][ty * 4];
            float4 b = *(const float4*)&Bs[k][tx * 4];
            float av[4] = {a.x, a.y, a.z, a.w};
            float bv[4] = {b.x, b.y, b.z, b.w};
            #pragma unroll
            for (int i = 0; i < 4; i++)
                #pragma unroll
                for (int j = 0; j < 4; j++)
                    acc[i][j] += av[i] * bv[j];
        }
        __syncthreads();
    }

    #pragma unroll
    for (int i = 0; i < 4; i++) {
        int r = r0 + ty * 4 + i;
        #pragma unroll
        for (int j = 0; j < 4; j++) {
            int c = c0 + tx * 4 + j;
            out[(size_t)r * G3 + c] = acc[i][j] + bih[c];
        }
    }

    if (is_dec && blockIdx.x == 0) {
        for (int q = tid; q < 64 * EE; q += 256) {
            int r = q >> 8, e = q & 255;
            g_Ah[(size_t)(r0 + r) * KAB + HH + e] =
                __float2half_rn(emb[(size_t)sidx[r] * EE + e]);
        }
    }
}

// ---------------- persistent fused GRU: 64 CTAs x 8 j-cols -------------------
// lane = jl(2b)|ksec(2b)|bb0(1b); warp owns h rows [8w,8w+8) (warp-local staging).
// Each thread: 2 j-groups (jl, jl+4) x 4 b x 3 gates over a 128-wide K quarter.
#define FMA2(acc, a, b) asm("fma.rn.f32x2 %0, %1, %2, %0;" : "+l"(acc) : "l"(a), "l"(b))
__device__ __forceinline__ float hsum2(u64 v) {
    float lo = __uint_as_float((unsigned)(v & 0xffffffffull));
    float hi = __uint_as_float((unsigned)(v >> 32));
    return lo + hi;
}

#define WREG 3184                          // 24 rows x 132 = 3168, pad -> mod32=16
#define HREG 8456                          // mod32=8
#define GRU_SMEM ((4*WREG + 4*HREG) * 4)   // 186,240 B

__device__ __forceinline__ void load_whh(float* w_s, const float* __restrict__ Whh,
                                         int jbase, int tid)
{
    for (int i = tid; i < 3072; i += 256) {        // float4 units: 3g x 8j x 128k4
        int g  = i >> 10;
        int jj = (i >> 7) & 7;
        int k4 = i & 127;
        float4 v = *(const float4*)(Whh + ((size_t)(g * HH + jbase + jj)) * HH + k4 * 4);
        *(float4*)&w_s[(k4 >> 5) * WREG + (g * 8 + jj) * 132 + (k4 & 31) * 4] = v;
    }
}

__global__ void __launch_bounds__(256, 1)
k_gru_persist(const float* __restrict__ enc_Whh, const float* __restrict__ enc_bhh,
              const float* __restrict__ dec_Whh, const float* __restrict__ dec_bhh,
              const int*   __restrict__ lens)
{
    extern __shared__ float sm[];
    float* w_s = sm;
    float* h_s = sm + 4 * WREG;

    int tid  = threadIdx.x;
    int lane = tid & 31, warp = tid >> 5;
    int jl   = lane & 3;
    int ksec = (lane >> 2) & 3;
    int bb0  = lane >> 4;
    int bblk = (warp << 1) | bb0;
    int b0   = bblk * 4;
    int jbase = blockIdx.x * 8;
    int j1   = jbase + jl;
    int j2   = j1 + 4;
    int jr1 = j1 >> 7, jin1 = j1 & 127;
    int jr2 = j2 >> 7, jin2 = j2 & 127;
    bool writer = (ksec == 0);

    unsigned base = g_base;
    int lenb[4];
    #pragma unroll
    for (int bi = 0; bi < 4; bi++) lenb[bi] = lens[b0 + bi];

    load_whh(w_s, enc_Whh, jbase, tid);
    const float* bhh = enc_bhh;
    float b1r = bhh[j1], b1z = bhh[j1 + HH], b1n = bhh[j1 + 2 * HH];
    float b2r = bhh[j2], b2z = bhh[j2 + HH], b2n = bhh[j2 + 2 * HH];
    __syncthreads();

    for (int s = 0; s < NSTEP; s++) {
        if (s == TT) {
            __syncthreads();
            load_whh(w_s, dec_Whh, jbase, tid);
            bhh = dec_bhh;
            b1r = bhh[j1]; b1z = bhh[j1 + HH]; b1n = bhh[j1 + 2 * HH];
            b2r = bhh[j2]; b2z = bhh[j2 + HH]; b2n = bhh[j2 + 2 * HH];
            __syncthreads();
        }

        const float* __restrict__ hin  = g_h[s & 1];
        float* __restrict__       hout = g_h[(s + 1) & 1];
        const float* __restrict__ xg   = (s < TT)
            ? g_xg + (size_t)s * BB * G3
            : g_yg + (size_t)(s - TT) * BB * G3;

        // xg prefetch (writers): overlap latency with staging
        float pxr[2][4], pxz[2][4], pxn[2][4];
        if (writer) {
            #pragma unroll
            for (int bi = 0; bi < 4; bi++) {
                size_t xb = (size_t)(b0 + bi) * G3;
                pxr[0][bi] = xg[xb + j1];
                pxz[0][bi] = xg[xb + j1 + HH];
                pxn[0][bi] = xg[xb + j1 + 2 * HH];
                pxr[1][bi] = xg[xb + j2];
                pxz[1][bi] = xg[xb + j2 + HH];
                pxn[1][bi] = xg[xb + j2 + 2 * HH];
            }
        }

        // warp-local h staging (rows [8w, 8w+8))
        {
            const float4* hin4 = (const float4*)hin;
            #pragma unroll
            for (int i = 0; i < 32; i++) {
                int f4 = i * 32 + lane;
                int bloc = f4 >> 7;
                int k4 = f4 & 127;
                float4 v = hin4[(warp * 8 + bloc) * 128 + k4];
                *(float4*)&h_s[(k4 >> 5) * HREG + (warp * 8 + bloc) * 132 + (k4 & 31) * 4] = v;
            }
        }

        u64 acc[2][4][3] = {};
        const float* hp = h_s + ksec * HREG + b0 * 132;
        const float* wp = w_s + ksec * WREG + jl * 132;
        #pragma unroll 2
        for (int kin = 0; kin < 32; kin++) {
            ulonglong2 wa0 = *(const ulonglong2*)&wp[0    + kin * 4];
            ulonglong2 wa1 = *(const ulonglong2*)&wp[1056 + kin * 4];
            ulonglong2 wa2 = *(const ulonglong2*)&wp[2112 + kin * 4];
            ulonglong2 wb0 = *(const ulonglong2*)&wp[528  + kin * 4];
            ulonglong2 wb1 = *(const ulonglong2*)&wp[1584 + kin * 4];
            ulonglong2 wb2 = *(const ulonglong2*)&wp[2640 + kin * 4];
            #pragma unroll
            for (int bi = 0; bi < 4; bi++) {
                ulonglong2 h = *(const ulonglong2*)&hp[bi * 132 + kin * 4];
                FMA2(acc[0][bi][0], h.x, wa0.x); FMA2(acc[0][bi][0], h.y, wa0.y);
                FMA2(acc[0][bi][1], h.x, wa1.x); FMA2(acc[0][bi][1], h.y, wa1.y);
                FMA2(acc[0][bi][2], h.x, wa2.x); FMA2(acc[0][bi][2], h.y, wa2.y);
                FMA2(acc[1][bi][0], h.x, wb0.x); FMA2(acc[1][bi][0], h.y, wb0.y);
                FMA2(acc[1][bi][1], h.x, wb1.x); FMA2(acc[1][bi][1], h.y, wb1.y);
                FMA2(acc[1][bi][2], h.x, wb2.x); FMA2(acc[1][bi][2], h.y, wb2.y);
            }
        }

        float red[2][4][3];
        #pragma unroll
        for (int jg = 0; jg < 2; jg++)
            #pragma unroll
            for (int bi = 0; bi < 4; bi++)
                #pragma unroll
                for (int g = 0; g < 3; g++) {
                    float f = hsum2(acc[jg][bi][g]);
                    f += __shfl_xor_sync(0xffffffffu, f, 4);
                    f += __shfl_xor_sync(0xffffffffu, f, 8);
                    red[jg][bi][g] = f;
                }

        if (writer) {
            #pragma unroll
            for (int jg = 0; jg < 2; jg++) {
                int j   = jg ? j2 : j1;
                int jr  = jg ? jr2 : jr1;
                int jin = jg ? jin2 : jin1;
                float bR = jg ? b2r : b1r;
                float bZ = jg ? b2z : b1z;
                float bN = jg ? b2n : b1n;
                #pragma unroll
                for (int bi = 0; bi < 4; bi++) {
                    int b = b0 + bi;
                    float accR = red[jg][bi][0] + bR;
                    float accZ = red[jg][bi][1] + bZ;
                    float accN = red[jg][bi][2] + bN;
                    float rg = 1.f / (1.f + expf(-(pxr[jg][bi] + accR)));
                    float zg = 1.f / (1.f + expf(-(pxz[jg][bi] + accZ)));
                    float ng = tanhf(pxn[jg][bi] + rg * accN);
                    float hold = h_s[jr * HREG + b * 132 + jin];
                    float hv = (1.f - zg) * ng + zg * hold;
                    if (s < TT && s >= lenb[bi]) hv = hold;
                    hout[(size_t)b * HH + j] = hv;
                    if (s >= TT) g_Ah[((size_t)(s - TT) * BB + b) * KAB + j] = __float2half_rn(hv);
                }
            }
        }

        if (s == NSTEP - 1) break;
        __syncthreads();
        if (tid == 0) {
            __threadfence();
            unsigned target = base + (unsigned)NCTA_GRU * (unsigned)(s + 1);
            asm volatile("red.relaxed.gpu.global.add.u32 [%0], %1;"
                         :: "l"(&g_cnt2), "r"(1u) : "memory");
            unsigned v;
            do {
                asm volatile("ld.acquire.gpu.u32 %0, [%1];" : "=r"(v) : "l"(&g_cnt2) : "memory");
            } while ((int)(v - target) < 0);
        }
        __syncthreads();
    }
}

// ---------------- logits wmma 128x128 (occ 2), 3-stage, fused lse ------------
#define LDSH 72
#define STAGE_H (128 * LDSH)
#define NCHUNK 12
#define LOGITS_SMEM (1024 + 6 * STAGE_H * 2)

__device__ __forceinline__ void load_chunk_l(int ck, __half* dA, __half* dB,
                                             int m0, int n0, int tid)
{
    uint32_t a32 = smem_u32(dA), b32 = smem_u32(dB);
    const char* Ab = (const char*)g_Ah;
    const char* Bb = (const char*)g_Wh;
    size_t koff = (size_t)ck * 64 * 2;
    #pragma unroll
    for (int i = 0; i < 4; i++) {
        int idx = tid + i * 256;
        int r = idx >> 3, cb = idx & 7;
        cp_async16(a32 + (r * LDSH + cb * 8) * 2,
                   Ab + ((size_t)(m0 + r) * KAB) * 2 + koff + cb * 16);
    }
    #pragma unroll
    for (int i = 0; i < 4; i++) {
        int idx = tid + i * 256;
        int r = idx >> 3, cb = idx & 7;
        cp_async16(b32 + (r * LDSH + cb * 8) * 2,
                   Bb + ((size_t)(n0 + r) * KAB) * 2 + koff + cb * 16);
    }
}

__global__ void __launch_bounds__(256, 2)
k_logits_mma(const float* __restrict__ bout, float* __restrict__ dout)
{
    extern __shared__ char smraw[];
    __shared__ float bias_s[128];

    uint32_t sb0 = smem_u32(smraw);
    uint32_t sb  = (sb0 + 1023) & ~1023u;
    __half* smh = (__half*)(smraw + (sb - sb0));
    __half* Abuf[3] = { smh,                smh + 2 * STAGE_H, smh + 4 * STAGE_H };
    __half* Bbuf[3] = { smh + STAGE_H,      smh + 3 * STAGE_H, smh + 5 * STAGE_H };

    int tid = threadIdx.x, wid = tid >> 5;
    int n0 = blockIdx.x * 128;
    int m0 = blockIdx.y * 128;
    int wm = wid & 1;
    int wn = wid >> 1;

    if (tid < 128) bias_s[tid] = bout[n0 + tid];

    wmma::fragment<wmma::accumulator, 16, 16, 16, float> acc[4][2];
    #pragma unroll
    for (int i = 0; i < 4; i++)
        #pragma unroll
        for (int j = 0; j < 2; j++) wmma::fill_fragment(acc[i][j], 0.f);

    load_chunk_l(0, Abuf[0], Bbuf[0], m0, n0, tid);
    CP_COMMIT();
    load_chunk_l(1, Abuf[1], Bbuf[1], m0, n0, tid);
    CP_COMMIT();

    for (int c = 0; c < NCHUNK; c++) {
        asm volatile("cp.async.wait_group 1;" ::: "memory");
        __syncthreads();

        const __half* Ab = Abuf[c % 3];
        const __half* Bb = Bbuf[c % 3];
        #pragma unroll
        for (int k = 0; k < 4; k++) {
            wmma::fragment<wmma::matrix_a, 16, 16, 16, __half, wmma::row_major> af[4];
            wmma::fragment<wmma::matrix_b, 16, 16, 16, __half, wmma::col_major> bf[2];
            #pragma unroll
            for (int mi = 0; mi < 4; mi++)
                wmma::load_matrix_sync(af[mi], Ab + (wm * 64 + mi * 16) * LDSH + k * 16, LDSH);
            #pragma unroll
            for (int ni = 0; ni < 2; ni++)
                wmma::load_matrix_sync(bf[ni], Bb + (wn * 32 + ni * 16) * LDSH + k * 16, LDSH);
            #pragma unroll
            for (int mi = 0; mi < 4; mi++)
                #pragma unroll
                for (int ni = 0; ni < 2; ni++)
                    wmma::mma_sync(acc[mi][ni], af[mi], bf[ni], acc[mi][ni]);
        }
        if (c + 2 < NCHUNK)
            load_chunk_l(c + 2, Abuf[(c + 2) % 3], Bbuf[(c + 2) % 3], m0, n0, tid);
        CP_COMMIT();
    }
    asm volatile("cp.async.wait_group 0;" ::: "memory");
    __syncthreads();

    // epilogue: C -> smem, bias + guarded store + per-row lse partials
    float* C = (float*)smh;                 // [128][132]
    #pragma unroll
    for (int mi = 0; mi < 4; mi++)
        #pragma unroll
        for (int ni = 0; ni < 2; ni++)
            wmma::store_matrix_sync(C + (wm * 64 + mi * 16) * 132 + wn * 32 + ni * 16,
                                    acc[mi][ni], 132, wmma::mem_row_major);
    __syncthreads();

    int row  = tid >> 1;
    int half = tid & 1;
    int grow = m0 + row;
    bool ok  = grow < MDEC;
    const float* crow = C + row * 132 + half * 64;
    const float* brow = bias_s + half * 64;
    float* orow = dout + BVOFF + (size_t)grow * VV + n0 + half * 64;

    float mx = -3.4e38f;
    #pragma unroll 4
    for (int c4 = 0; c4 < 64; c4 += 4) {
        float4 v = make_float4(crow[c4] + brow[c4], crow[c4+1] + brow[c4+1],
                               crow[c4+2] + brow[c4+2], crow[c4+3] + brow[c4+3]);
        mx = fmaxf(mx, fmaxf(fmaxf(v.x, v.y), fmaxf(v.z, v.w)));
        if (ok) *(float4*)(orow + c4) = v;
    }
    float sum = 0.f;
    #pragma unroll 4
    for (int c4 = 0; c4 < 64; c4 += 4) {
        sum += __expf(crow[c4]   + brow[c4]   - mx) + __expf(crow[c4+1] + brow[c4+1] - mx)
             + __expf(crow[c4+2] + brow[c4+2] - mx) + __expf(crow[c4+3] + brow[c4+3] - mx);
    }
    float mo = __shfl_xor_sync(0xffffffffu, mx, 1);
    float so = __shfl_xor_sync(0xffffffffu, sum, 1);
    float M = fmaxf(mx, mo);
    float S = sum * __expf(mx - M) + so * __expf(mo - M);
    if (half == 0 && ok) {
        g_pmax[(size_t)grow * NT + blockIdx.x] = M;
        g_psum[(size_t)grow * NT + blockIdx.x] = S;
    }
}

// ---------------- reduce lse partials (250 per row) --------------------------
__global__ void k_lse_red()
{
    int row = blockIdx.x * 8 + (threadIdx.x >> 5);
    int lane = threadIdx.x & 31;
    if (row >= MDEC) return;
    float M = -3.4e38f, S = 0.f;
    for (int j = lane; j < NT; j += 32) {
        float pm = g_pmax[(size_t)row * NT + j];
        float ps = g_psum[(size_t)row * NT + j];
        float nm = fmaxf(M, pm);
        S = S * __expf(M - nm) + ps * __expf(pm - nm);
        M = nm;
    }
    #pragma unroll
    for (int d = 16; d; d >>= 1) {
        float pm = __shfl_xor_sync(0xffffffffu, M, d);
        float ps = __shfl_xor_sync(0xffffffffu, S, d);
        float nm = fmaxf(M, pm);
        S = S * __expf(M - nm) + ps * __expf(pm - nm);
        M = nm;
    }
    if (lane == 0) g_lse[row] = M + logf(S);
}

// ---------------- masked NLL loss -------------------------------------------
__global__ void k_loss(const float* __restrict__ dout_r,
                       const int* __restrict__ y,
                       float* __restrict__ dout_w,
                       int has_slot)
{
    __shared__ float rs[256];
    __shared__ int   rc[256];
    int tid = threadIdx.x;
    float acc = 0.f; int cnt = 0;
    for (int r = tid; r < MDEC; r += 256) {
        int tgt = y[r + BB];
        if (tgt != 0) {
            float logit = dout_r[BVOFF + (size_t)r * VV + tgt];
            acc += g_lse[r] - logit;
            cnt++;
        }
    }
    rs[tid] = acc; rc[tid] = cnt; __syncthreads();
    for (int s = 128; s; s >>= 1) {
        if (tid < s) { rs[tid] += rs[tid + s]; rc[tid] += rc[tid + s]; }
        __syncthreads();
    }
    if (tid == 0 && has_slot) dout_w[LOSS_IDX] = rs[0] / (float)max(rc[0], 1);
}

// ---------------- launch ------------------------------------------------------
extern "C" void kernel_launch(void* const* d_in, const int* in_sizes, int n_in,
                              void* d_out, int out_size)
{
    const int*   x        = (const int*)  d_in[0];
    const int*   x_lens   = (const int*)  d_in[1];
    const int*   y        = (const int*)  d_in[2];
    const float* emb      = (const float*)d_in[3];
    const float* enc_Wih  = (const float*)d_in[4];
    const float* enc_Whh  = (const float*)d_in[5];
    const float* enc_bih  = (const float*)d_in[6];
    const float* enc_bhh  = (const float*)d_in[7];
    const float* dec_Wih  = (const float*)d_in[8];
    const float* dec_Whh  = (const float*)d_in[9];
    const float* dec_bih  = (const float*)d_in[10];
    const float* dec_bhh  = (const float*)d_in[11];
    const float* Wout     = (const float*)d_in[12];
    const float* bout     = (const float*)d_in[13];
    float* out = (float*)d_out;

    (void)in_sizes; (void)n_in;

    cudaFuncSetAttribute(k_gru_persist,
                         cudaFuncAttributeMaxDynamicSharedMemorySize, GRU_SMEM);
    cudaFuncSetAttribute(k_logits_mma,
                         cudaFuncAttributeMaxDynamicSharedMemorySize, LOGITS_SMEM);

    k_gates<<<dim3(24, GATES_PLANES), 256>>>(
        x, y, emb, enc_Wih, enc_bih, dec_Wih, dec_bih, Wout, out);

    k_gru_persist<<<NCTA_GRU, 256, GRU_SMEM>>>(enc_Whh, enc_bhh, dec_Whh, dec_bhh, x_lens);

    k_logits_mma<<<dim3(NT, MPAD / 128), 256, LOGITS_SMEM>>>(bout, out);

    k_lse_red<<<(MDEC + 7) / 8, 256>>>();
    int has_slot = (out_size > (int)LOSS_IDX) ? 1 : 0;
    k_loss<<<1, 256>>>(out, y, out, has_slot);
}

// round 17
// speedup vs baseline: 1.2316x; 1.2316x over previous
#include <cuda_runtime.h>
#include <cuda_fp16.h>
#include <mma.h>
#include <cstdint>
#include <math.h>

using namespace nvcuda;

#define TT 64
#define BB 64
#define EE 256
#define HH 512
#define VV 32000
#define G3 1536                      // 3H
#define KAB 768                      // H + E
#define MENC (TT*BB)                 // 4096
#define MDEC ((TT-1)*BB)             // 4032
#define MPAD 4096
#define NT 250                       // N tiles of 128
#define BVOFF ((size_t)BB*VV)
#define LOSS_IDX ((size_t)TT*BB*VV)
#define NSTEP (2*TT - 1)
#define NCTA_GRU 128
#define CONVW_BLKS ((VV * KAB) / 8 / 256)          // 12000
#define CONVW_PLANES ((CONVW_BLKS + 23) / 24)      // 500
#define ZERO_SLOTS 526336
#define ZERO_PLANES ((ZERO_SLOTS + 24*256 - 1) / (24*256))   // 86
#define GATES_PLANES (127 + CONVW_PLANES + ZERO_PLANES)      // 713

typedef unsigned long long u64;

// ---------------- scratch -----------------------------------------------------
__device__ float g_xg[MENC * G3];
__device__ float g_yg[MDEC * G3];
__device__ __align__(256) __half g_Ah[MPAD * KAB];
__device__ __align__(256) __half g_Wh[VV * KAB];
__device__ __align__(256) float g_h [2][BB * HH];
__device__ float g_pmax[MDEC * NT];
__device__ float g_psum[MDEC * NT];
__device__ float g_loss_sum;
__device__ int   g_loss_cnt;
__device__ unsigned g_cnt2 = 0;                // monotonic barrier counter
__device__ unsigned g_base = 0;                // snapshot (set in gates kernel)

// ================= helpers ===================================================
__device__ __forceinline__ uint32_t smem_u32(const void* p) {
    uint32_t a;
    asm("{ .reg .u64 t; cvta.to.shared.u64 t, %1; cvt.u32.u64 %0, t; }" : "=r"(a) : "l"(p));
    return a;
}
__device__ __forceinline__ void cp_async16(uint32_t dst, const void* src) {
    asm volatile("cp.async.cg.shared.global [%0], [%1], 16;" :: "r"(dst), "l"(src));
}
#define CP_COMMIT() asm volatile("cp.async.commit_group;" ::: "memory")

// ------- merged: gate GEMMs ∪ Wout fp32->fp16 ∪ zero-init --------------------
__global__ void k_gates(const int* __restrict__ x, const int* __restrict__ y,
                        const float* __restrict__ emb,
                        const float* __restrict__ eW, const float* __restrict__ eb,
                        const float* __restrict__ dW, const float* __restrict__ db,
                        const float* __restrict__ Wout,
                        float* __restrict__ dout)
{
    __shared__ float As[32][64];
    __shared__ float Bs[32][64];
    __shared__ int   sidx[64];

    int by = blockIdx.y;
    int tid = threadIdx.x;

    if (by >= 127 + CONVW_PLANES) {        // ---- zero planes ----
        int chunk = (by - (127 + CONVW_PLANES)) * 24 + blockIdx.x;
        if (chunk == 0 && tid == 0) { g_loss_sum = 0.f; g_loss_cnt = 0; }
        size_t slot = (size_t)chunk * 256 + tid;
        if (slot < ZERO_SLOTS) {
            float4 z = make_float4(0.f, 0.f, 0.f, 0.f);
            if (slot < 512000)        ((float4*)dout)[slot] = z;
            else if (slot < 520192)   ((float4*)g_h[0])[slot - 512000] = z;
            else                      ((float4*)(g_Ah + (size_t)MDEC * KAB))[slot - 520192] = z;
        }
        return;
    }

    if (by >= 127) {                       // ---- convW planes ----
        if (by == 127 && blockIdx.x == 0 && tid == 0)
            g_base = *(volatile unsigned*)&g_cnt2;
        int chunk = (by - 127) * 24 + blockIdx.x;
        size_t i = ((size_t)chunk * 256 + tid) * 8;
        if (i < (size_t)VV * KAB) {
            float4 a = *(const float4*)(Wout + i);
            float4 b = *(const float4*)(Wout + i + 4);
            __half2 h0 = __floats2half2_rn(a.x, a.y);
            __half2 h1 = __floats2half2_rn(a.z, a.w);
            __half2 h2 = __floats2half2_rn(b.x, b.y);
            __half2 h3 = __floats2half2_rn(b.z, b.w);
            uint4 o;
            o.x = *(uint32_t*)&h0; o.y = *(uint32_t*)&h1;
            o.z = *(uint32_t*)&h2; o.w = *(uint32_t*)&h3;
            *(uint4*)(g_Wh + i) = o;
        }
        return;
    }

    int is_dec = (by >= 64);
    const int*   idx = is_dec ? y  : x;
    const float* Wih = is_dec ? dW : eW;
    const float* bih = is_dec ? db : eb;
    float* __restrict__ out = is_dec ? g_yg : g_xg;
    int r0 = (is_dec ? (by - 64) : by) * 64;
    int c0 = blockIdx.x * 64;

    if (tid < 64) sidx[tid] = idx[r0 + tid];
    __syncthreads();

    int tx = tid & 15, ty = tid >> 4;
    float acc[4][4] = {};

    for (int k0 = 0; k0 < EE; k0 += 32) {
        #pragma unroll
        for (int fi = tid; fi < 512; fi += 256) {
            int r = fi >> 3, kq = (fi & 7) * 4;
            float4 v = *(const float4*)(emb + (size_t)sidx[r] * EE + k0 + kq);
            As[kq + 0][r] = v.x; As[kq + 1][r] = v.y;
            As[kq + 2][r] = v.z; As[kq + 3][r] = v.w;
        }
        #pragma unroll
        for (int fi = tid; fi < 512; fi += 256) {
            int c = fi >> 3, kq = (fi & 7) * 4;
            float4 v = *(const float4*)(Wih + (size_t)(c0 + c) * EE + k0 + kq);
            Bs[kq + 0][c] = v.x; Bs[kq + 1][c] = v.y;
            Bs[kq + 2][c] = v.z; Bs[kq + 3][c] = v.w;
        }
        __syncthreads();
        #pragma unroll
        for (int k = 0; k < 32; k++) {
            float4 a = *(const float4*)&As[k][ty * 4];
            float4 b = *(const float4*)&Bs[k][tx * 4];
            float av[4] = {a.x, a.y, a.z, a.w};
            float bv[4] = {b.x, b.y, b.z, b.w};
            #pragma unroll
            for (int i = 0; i < 4; i++)
                #pragma unroll
                for (int j = 0; j < 4; j++)
                    acc[i][j] += av[i] * bv[j];
        }
        __syncthreads();
    }

    #pragma unroll
    for (int i = 0; i < 4; i++) {
        int r = r0 + ty * 4 + i;
        #pragma unroll
        for (int j = 0; j < 4; j++) {
            int c = c0 + tx * 4 + j;
            out[(size_t)r * G3 + c] = acc[i][j] + bih[c];
        }
    }

    if (is_dec && blockIdx.x == 0) {
        for (int q = tid; q < 64 * EE; q += 256) {
            int r = q >> 8, e = q & 255;
            g_Ah[(size_t)(r0 + r) * KAB + HH + e] =
                __float2half_rn(emb[(size_t)sidx[r] * EE + e]);
        }
    }
}

// ---------------- persistent fused GRU: 128 CTAs x 4 j-cols (R13 config) -----
#define FMA2(acc, a, b) asm("fma.rn.f32x2 %0, %1, %2, %0;" : "+l"(acc) : "l"(a), "l"(b))
__device__ __forceinline__ float hsum2(u64 v) {
    float lo = __uint_as_float((unsigned)(v & 0xffffffffull));
    float hi = __uint_as_float((unsigned)(v >> 32));
    return lo + hi;
}

#define WREG 1584
#define HREG 8456
#define GRU_SMEM ((4*WREG + 4*HREG) * 4)

__device__ __forceinline__ void load_whh(float* w_s, const float* __restrict__ Whh,
                                         int jbase, int tid)
{
    for (int i = tid; i < 1536; i += 256) {
        int g  = i >> 9;
        int jj = (i >> 7) & 3;
        int k4 = i & 127;
        float4 v = *(const float4*)(Whh + ((size_t)(g * HH + jbase + jj)) * HH + k4 * 4);
        *(float4*)&w_s[(k4 >> 5) * WREG + (g * 4 + jj) * 132 + (k4 & 31) * 4] = v;
    }
}

__global__ void __launch_bounds__(256, 1)
k_gru_persist(const float* __restrict__ enc_Whh, const float* __restrict__ enc_bhh,
              const float* __restrict__ dec_Whh, const float* __restrict__ dec_bhh,
              const int*   __restrict__ lens)
{
    extern __shared__ float sm[];
    float* w_s = sm;
    float* h_s = sm + 4 * WREG;

    int tid  = threadIdx.x;
    int lane = tid & 31, warp = tid >> 5;
    int jl   = lane & 3;
    int ksec = (lane >> 2) & 3;
    int bb0  = lane >> 4;
    int bblk = (warp << 1) | bb0;
    int b0   = bblk * 4;
    int jbase = blockIdx.x * 4;
    int j    = jbase + jl;
    int jr   = j >> 7, jin = j & 127;
    bool writer = (ksec == 0);

    unsigned base = g_base;
    int lenb[4];
    #pragma unroll
    for (int bi = 0; bi < 4; bi++) lenb[bi] = lens[b0 + bi];

    load_whh(w_s, enc_Whh, jbase, tid);
    const float* bhh = enc_bhh;
    float br = bhh[j], bz = bhh[j + HH], bn = bhh[j + 2 * HH];
    __syncthreads();

    for (int s = 0; s < NSTEP; s++) {
        if (s == TT) {
            __syncthreads();
            load_whh(w_s, dec_Whh, jbase, tid);
            bhh = dec_bhh;
            br = bhh[j]; bz = bhh[j + HH]; bn = bhh[j + 2 * HH];
            __syncthreads();
        }

        const float* __restrict__ hin  = g_h[s & 1];
        float* __restrict__       hout = g_h[(s + 1) & 1];
        const float* __restrict__ xg   = (s < TT)
            ? g_xg + (size_t)s * BB * G3
            : g_yg + (size_t)(s - TT) * BB * G3;

        float pxr[4], pxz[4], pxn[4];
        if (writer) {
            #pragma unroll
            for (int bi = 0; bi < 4; bi++) {
                size_t xb = (size_t)(b0 + bi) * G3 + j;
                pxr[bi] = xg[xb];
                pxz[bi] = xg[xb + HH];
                pxn[bi] = xg[xb + 2 * HH];
            }
        }

        {
            const float4* hin4 = (const float4*)hin;
            #pragma unroll
            for (int i = 0; i < 32; i++) {
                int f4 = i * 32 + lane;
                int bloc = f4 >> 7;
                int k4 = f4 & 127;
                float4 v = hin4[(warp * 8 + bloc) * 128 + k4];
                *(float4*)&h_s[(k4 >> 5) * HREG + (warp * 8 + bloc) * 132 + (k4 & 31) * 4] = v;
            }
        }

        u64 acc[4][3] = {};
        const float* hp = h_s + ksec * HREG + b0 * 132;
        const float* wp = w_s + ksec * WREG + jl * 132;
        #pragma unroll 4
        for (int kin = 0; kin < 32; kin++) {
            ulonglong2 w0 = *(const ulonglong2*)&wp[0    + kin * 4];
            ulonglong2 w1 = *(const ulonglong2*)&wp[528  + kin * 4];
            ulonglong2 w2 = *(const ulonglong2*)&wp[1056 + kin * 4];
            #pragma unroll
            for (int bi = 0; bi < 4; bi++) {
                ulonglong2 h = *(const ulonglong2*)&hp[bi * 132 + kin * 4];
                FMA2(acc[bi][0], h.x, w0.x); FMA2(acc[bi][0], h.y, w0.y);
                FMA2(acc[bi][1], h.x, w1.x); FMA2(acc[bi][1], h.y, w1.y);
                FMA2(acc[bi][2], h.x, w2.x); FMA2(acc[bi][2], h.y, w2.y);
            }
        }

        float red[4][3];
        #pragma unroll
        for (int bi = 0; bi < 4; bi++)
            #pragma unroll
            for (int g = 0; g < 3; g++) {
                float f = hsum2(acc[bi][g]);
                f += __shfl_xor_sync(0xffffffffu, f, 4);
                f += __shfl_xor_sync(0xffffffffu, f, 8);
                red[bi][g] = f;
            }

        if (writer) {
            #pragma unroll
            for (int bi = 0; bi < 4; bi++) {
                int b = b0 + bi;
                float accR = red[bi][0] + br;
                float accZ = red[bi][1] + bz;
                float accN = red[bi][2] + bn;
                float rg = 1.f / (1.f + expf(-(pxr[bi] + accR)));
                float zg = 1.f / (1.f + expf(-(pxz[bi] + accZ)));
                float ng = tanhf(pxn[bi] + rg * accN);
                float hold = h_s[jr * HREG + b * 132 + jin];
                float hv = (1.f - zg) * ng + zg * hold;
                if (s < TT && s >= lenb[bi]) hv = hold;
                hout[(size_t)b * HH + j] = hv;
                if (s >= TT) g_Ah[((size_t)(s - TT) * BB + b) * KAB + j] = __float2half_rn(hv);
            }
        }

        if (s == NSTEP - 1) break;
        __syncthreads();
        if (tid == 0) {
            __threadfence();
            unsigned target = base + 128u * (unsigned)(s + 1);
            asm volatile("red.relaxed.gpu.global.add.u32 [%0], %1;"
                         :: "l"(&g_cnt2), "r"(1u) : "memory");
            unsigned v;
            do {
                asm volatile("ld.acquire.gpu.u32 %0, [%1];" : "=r"(v) : "l"(&g_cnt2) : "memory");
            } while ((int)(v - target) < 0);
        }
        __syncthreads();
    }
}

// ---------------- logits wmma 128x128 (occ 2), 3-stage, fused lse ------------
#define LDSH 72
#define STAGE_H (128 * LDSH)
#define NCHUNK 12
#define LOGITS_SMEM (1024 + 6 * STAGE_H * 2)

__device__ __forceinline__ void load_chunk_l(int ck, __half* dA, __half* dB,
                                             int m0, int n0, int tid)
{
    uint32_t a32 = smem_u32(dA), b32 = smem_u32(dB);
    const char* Ab = (const char*)g_Ah;
    const char* Bb = (const char*)g_Wh;
    size_t koff = (size_t)ck * 64 * 2;
    #pragma unroll
    for (int i = 0; i < 4; i++) {
        int idx = tid + i * 256;
        int r = idx >> 3, cb = idx & 7;
        cp_async16(a32 + (r * LDSH + cb * 8) * 2,
                   Ab + ((size_t)(m0 + r) * KAB) * 2 + koff + cb * 16);
    }
    #pragma unroll
    for (int i = 0; i < 4; i++) {
        int idx = tid + i * 256;
        int r = idx >> 3, cb = idx & 7;
        cp_async16(b32 + (r * LDSH + cb * 8) * 2,
                   Bb + ((size_t)(n0 + r) * KAB) * 2 + koff + cb * 16);
    }
}

__global__ void __launch_bounds__(256, 2)
k_logits_mma(const float* __restrict__ bout, float* __restrict__ dout)
{
    extern __shared__ char smraw[];
    __shared__ float bias_s[128];

    uint32_t sb0 = smem_u32(smraw);
    uint32_t sb  = (sb0 + 1023) & ~1023u;
    __half* smh = (__half*)(smraw + (sb - sb0));
    __half* Abuf[3] = { smh,                smh + 2 * STAGE_H, smh + 4 * STAGE_H };
    __half* Bbuf[3] = { smh + STAGE_H,      smh + 3 * STAGE_H, smh + 5 * STAGE_H };

    int tid = threadIdx.x, wid = tid >> 5;
    int n0 = blockIdx.x * 128;
    int m0 = blockIdx.y * 128;
    int wm = wid & 1;
    int wn = wid >> 1;

    if (tid < 128) bias_s[tid] = bout[n0 + tid];

    wmma::fragment<wmma::accumulator, 16, 16, 16, float> acc[4][2];
    #pragma unroll
    for (int i = 0; i < 4; i++)
        #pragma unroll
        for (int j = 0; j < 2; j++) wmma::fill_fragment(acc[i][j], 0.f);

    load_chunk_l(0, Abuf[0], Bbuf[0], m0, n0, tid);
    CP_COMMIT();
    load_chunk_l(1, Abuf[1], Bbuf[1], m0, n0, tid);
    CP_COMMIT();

    for (int c = 0; c < NCHUNK; c++) {
        asm volatile("cp.async.wait_group 1;" ::: "memory");
        __syncthreads();

        const __half* Ab = Abuf[c % 3];
        const __half* Bb = Bbuf[c % 3];
        #pragma unroll
        for (int k = 0; k < 4; k++) {
            wmma::fragment<wmma::matrix_a, 16, 16, 16, __half, wmma::row_major> af[4];
            wmma::fragment<wmma::matrix_b, 16, 16, 16, __half, wmma::col_major> bf[2];
            #pragma unroll
            for (int mi = 0; mi < 4; mi++)
                wmma::load_matrix_sync(af[mi], Ab + (wm * 64 + mi * 16) * LDSH + k * 16, LDSH);
            #pragma unroll
            for (int ni = 0; ni < 2; ni++)
                wmma::load_matrix_sync(bf[ni], Bb + (wn * 32 + ni * 16) * LDSH + k * 16, LDSH);
            #pragma unroll
            for (int mi = 0; mi < 4; mi++)
                #pragma unroll
                for (int ni = 0; ni < 2; ni++)
                    wmma::mma_sync(acc[mi][ni], af[mi], bf[ni], acc[mi][ni]);
        }
        if (c + 2 < NCHUNK)
            load_chunk_l(c + 2, Abuf[(c + 2) % 3], Bbuf[(c + 2) % 3], m0, n0, tid);
        CP_COMMIT();
    }
    asm volatile("cp.async.wait_group 0;" ::: "memory");
    __syncthreads();

    // epilogue: C -> smem, bias + guarded store + per-row lse partials
    float* C = (float*)smh;                 // [128][132]
    #pragma unroll
    for (int mi = 0; mi < 4; mi++)
        #pragma unroll
        for (int ni = 0; ni < 2; ni++)
            wmma::store_matrix_sync(C + (wm * 64 + mi * 16) * 132 + wn * 32 + ni * 16,
                                    acc[mi][ni], 132, wmma::mem_row_major);
    __syncthreads();

    int row  = tid >> 1;
    int half = tid & 1;
    int grow = m0 + row;
    bool ok  = grow < MDEC;
    const float* crow = C + row * 132 + half * 64;
    const float* brow = bias_s + half * 64;
    float* orow = dout + BVOFF + (size_t)grow * VV + n0 + half * 64;

    float mx = -3.4e38f;
    #pragma unroll 4
    for (int c4 = 0; c4 < 64; c4 += 4) {
        float4 v = make_float4(crow[c4] + brow[c4], crow[c4+1] + brow[c4+1],
                               crow[c4+2] + brow[c4+2], crow[c4+3] + brow[c4+3]);
        mx = fmaxf(mx, fmaxf(fmaxf(v.x, v.y), fmaxf(v.z, v.w)));
        if (ok) *(float4*)(orow + c4) = v;
    }
    float sum = 0.f;
    #pragma unroll 4
    for (int c4 = 0; c4 < 64; c4 += 4) {
        sum += __expf(crow[c4]   + brow[c4]   - mx) + __expf(crow[c4+1] + brow[c4+1] - mx)
             + __expf(crow[c4+2] + brow[c4+2] - mx) + __expf(crow[c4+3] + brow[c4+3] - mx);
    }
    float mo = __shfl_xor_sync(0xffffffffu, mx, 1);
    float so = __shfl_xor_sync(0xffffffffu, sum, 1);
    float M = fmaxf(mx, mo);
    float S = sum * __expf(mx - M) + so * __expf(mo - M);
    if (half == 0 && ok) {
        g_pmax[(size_t)grow * NT + blockIdx.x] = M;
        g_psum[(size_t)grow * NT + blockIdx.x] = S;
    }
}

// ---------------- reduce lse partials + fused NLL loss partials --------------
__global__ void k_lse_red(const float* __restrict__ dout, const int* __restrict__ y)
{
    int row = blockIdx.x * 8 + (threadIdx.x >> 5);
    int lane = threadIdx.x & 31;
    if (row >= MDEC) return;
    float M = -3.4e38f, S = 0.f;
    for (int jt = lane; jt < NT; jt += 32) {
        float pm = g_pmax[(size_t)row * NT + jt];
        float ps = g_psum[(size_t)row * NT + jt];
        float nm = fmaxf(M, pm);
        S = S * __expf(M - nm) + ps * __expf(pm - nm);
        M = nm;
    }
    #pragma unroll
    for (int d = 16; d; d >>= 1) {
        float pm = __shfl_xor_sync(0xffffffffu, M, d);
        float ps = __shfl_xor_sync(0xffffffffu, S, d);
        float nm = fmaxf(M, pm);
        S = S * __expf(M - nm) + ps * __expf(pm - nm);
        M = nm;
    }
    if (lane == 0) {
        int tgt = y[row + BB];
        if (tgt != 0) {
            float lse = M + logf(S);
            float logit = dout[BVOFF + (size_t)row * VV + tgt];
            atomicAdd(&g_loss_sum, lse - logit);
            atomicAdd(&g_loss_cnt, 1);
        }
    }
}

// ---------------- finalize loss ----------------------------------------------
__global__ void k_loss_fin(float* __restrict__ dout_w, int has_slot)
{
    if (has_slot) dout_w[LOSS_IDX] = g_loss_sum / (float)max(g_loss_cnt, 1);
}

// ---------------- launch ------------------------------------------------------
extern "C" void kernel_launch(void* const* d_in, const int* in_sizes, int n_in,
                              void* d_out, int out_size)
{
    const int*   x        = (const int*)  d_in[0];
    const int*   x_lens   = (const int*)  d_in[1];
    const int*   y        = (const int*)  d_in[2];
    const float* emb      = (const float*)d_in[3];
    const float* enc_Wih  = (const float*)d_in[4];
    const float* enc_Whh  = (const float*)d_in[5];
    const float* enc_bih  = (const float*)d_in[6];
    const float* enc_bhh  = (const float*)d_in[7];
    const float* dec_Wih  = (const float*)d_in[8];
    const float* dec_Whh  = (const float*)d_in[9];
    const float* dec_bih  = (const float*)d_in[10];
    const float* dec_bhh  = (const float*)d_in[11];
    const float* Wout     = (const float*)d_in[12];
    const float* bout     = (const float*)d_in[13];
    float* out = (float*)d_out;

    (void)in_sizes; (void)n_in;

    cudaFuncSetAttribute(k_gru_persist,
                         cudaFuncAttributeMaxDynamicSharedMemorySize, GRU_SMEM);
    cudaFuncSetAttribute(k_logits_mma,
                         cudaFuncAttributeMaxDynamicSharedMemorySize, LOGITS_SMEM);

    k_gates<<<dim3(24, GATES_PLANES), 256>>>(
        x, y, emb, enc_Wih, enc_bih, dec_Wih, dec_bih, Wout, out);

    k_gru_persist<<<NCTA_GRU, 256, GRU_SMEM>>>(enc_Whh, enc_bhh, dec_Whh, dec_bhh, x_lens);

    k_logits_mma<<<dim3(NT, MPAD / 128), 256, LOGITS_SMEM>>>(bout, out);

    k_lse_red<<<(MDEC + 7) / 8, 256>>>(out, y);
    int has_slot = (out_size > (int)LOSS_IDX) ? 1 : 0;
    k_loss_fin<<<1, 1>>>(out, has_slot);
}